// round 1
// baseline (speedup 1.0000x reference)
#include <cuda_runtime.h>
#include <cuda_bf16.h>

// kv scratch: 256 x 2048 fp32 = 2 MB (device global, allocation-free)
__device__ float g_kv[256 * 2048];

#define BM 64
#define BN 64
#define BK 16

// GEMM: kv[m, n] = sum_k x[m,k] * W[n,k] + bias[n]
// x: [256, 1024], W: [2048, 1024] row-major (both K-contiguous -> coalesced loads)
__global__ __launch_bounds__(256) void gemm_kernel(
    const float* __restrict__ x,
    const float* __restrict__ W,
    const float* __restrict__ bias,
    float* __restrict__ kv)
{
    __shared__ float As[BK][BM];   // transposed tiles: [k][m]
    __shared__ float Bs[BK][BN];   // [k][n]

    const int tid = threadIdx.x;          // 0..255
    const int m0  = blockIdx.y * BM;
    const int n0  = blockIdx.x * BN;

    const int tx = tid % 16;              // 16x16 thread grid
    const int ty = tid / 16;

    // load mapping: each thread loads one float4 of A and one of B per k-tile
    const int lrow  = tid >> 2;           // 0..63
    const int lcol4 = (tid & 3) << 2;     // 0,4,8,12

    const float* a_ptr = x + (m0 + lrow) * 1024 + lcol4;
    const float* b_ptr = W + (n0 + lrow) * 1024 + lcol4;

    float acc[4][4];
    #pragma unroll
    for (int i = 0; i < 4; i++)
        #pragma unroll
        for (int j = 0; j < 4; j++)
            acc[i][j] = 0.0f;

    for (int k0 = 0; k0 < 1024; k0 += BK) {
        float4 a = *reinterpret_cast<const float4*>(a_ptr + k0);
        float4 b = *reinterpret_cast<const float4*>(b_ptr + k0);

        As[lcol4 + 0][lrow] = a.x;
        As[lcol4 + 1][lrow] = a.y;
        As[lcol4 + 2][lrow] = a.z;
        As[lcol4 + 3][lrow] = a.w;
        Bs[lcol4 + 0][lrow] = b.x;
        Bs[lcol4 + 1][lrow] = b.y;
        Bs[lcol4 + 2][lrow] = b.z;
        Bs[lcol4 + 3][lrow] = b.w;
        __syncthreads();

        #pragma unroll
        for (int k = 0; k < BK; k++) {
            float4 av = *reinterpret_cast<const float4*>(&As[k][ty * 4]);
            float4 bv = *reinterpret_cast<const float4*>(&Bs[k][tx * 4]);
            float ar[4] = {av.x, av.y, av.z, av.w};
            float br[4] = {bv.x, bv.y, bv.z, bv.w};
            #pragma unroll
            for (int i = 0; i < 4; i++)
                #pragma unroll
                for (int j = 0; j < 4; j++)
                    acc[i][j] = fmaf(ar[i], br[j], acc[i][j]);
        }
        __syncthreads();
    }

    #pragma unroll
    for (int i = 0; i < 4; i++) {
        const int m = m0 + ty * 4 + i;
        #pragma unroll
        for (int j = 0; j < 4; j++) {
            const int n = n0 + tx * 4 + j;
            kv[m * 2048 + n] = acc[i][j] + bias[n];
        }
    }
}

// Per-row: s = dot(kv[b, 0:1024], q[b, :]); out[b, i] = kv[b, 1024+i] * s
__global__ __launch_bounds__(256) void epilogue_kernel(
    const float* __restrict__ kv,
    const float* __restrict__ q,
    float* __restrict__ out)
{
    const int b   = blockIdx.x;
    const int tid = threadIdx.x;   // 256

    const float* kvrow = kv + b * 2048;
    const float* qrow  = q  + b * 1024;

    // 1024 floats = 256 float4s -> one per thread
    float4 kk = reinterpret_cast<const float4*>(kvrow)[tid];
    float4 qq = reinterpret_cast<const float4*>(qrow)[tid];
    float s = kk.x * qq.x + kk.y * qq.y + kk.z * qq.z + kk.w * qq.w;

    // warp reduce
    #pragma unroll
    for (int off = 16; off > 0; off >>= 1)
        s += __shfl_xor_sync(0xFFFFFFFFu, s, off);

    __shared__ float red[8];
    __shared__ float s_total;
    const int wid = tid >> 5;
    const int lid = tid & 31;
    if (lid == 0) red[wid] = s;
    __syncthreads();
    if (wid == 0) {
        float v = (lid < 8) ? red[lid] : 0.0f;
        #pragma unroll
        for (int off = 4; off > 0; off >>= 1)
            v += __shfl_xor_sync(0xFFFFFFFFu, v, off);
        if (lid == 0) s_total = v;
    }
    __syncthreads();
    const float st = s_total;

    // out[b, :] = v_part * s ; 256 float4s
    float4 vv = reinterpret_cast<const float4*>(kvrow + 1024)[tid];
    float4 o;
    o.x = vv.x * st; o.y = vv.y * st; o.z = vv.z * st; o.w = vv.w * st;
    reinterpret_cast<float4*>(out + b * 1024)[tid] = o;
}

extern "C" void kernel_launch(void* const* d_in, const int* in_sizes, int n_in,
                              void* d_out, int out_size)
{
    const float* x  = (const float*)d_in[0];   // 256*1024
    const float* q  = (const float*)d_in[1];   // 256*1024
    const float* W  = (const float*)d_in[2];   // 2048*1024
    const float* bs = (const float*)d_in[3];   // 2048
    float* out = (float*)d_out;                // 256*1024

    float* kv;
    cudaGetSymbolAddress((void**)&kv, g_kv);

    dim3 grid(2048 / BN, 256 / BM);  // 32 x 4 = 128 CTAs
    gemm_kernel<<<grid, 256>>>(x, W, bs, kv);
    epilogue_kernel<<<256, 256>>>(kv, q, out);
}

// round 3
// speedup vs baseline: 2.1425x; 2.1425x over previous
#include <cuda_runtime.h>
#include <cuda_bf16.h>
#include <cstdint>

// ---------------------------------------------------------------------------
// Device scratch (allocation-free)
// ---------------------------------------------------------------------------
__device__ __align__(256) __nv_bfloat16 g_xhi[256 * 1024];
__device__ __align__(256) __nv_bfloat16 g_xlo[256 * 1024];
__device__ __align__(256) __nv_bfloat16 g_whi[2048 * 1024];
__device__ __align__(256) __nv_bfloat16 g_wlo[2048 * 1024];
__device__ __align__(256) float g_v[256 * 1024];     // v + bias
__device__ __align__(256) float g_sp[32 * 256];      // partial dots

// ---------------------------------------------------------------------------
// Helpers
// ---------------------------------------------------------------------------
__device__ __forceinline__ uint32_t smem_u32(const void* p) {
    uint32_t a;
    asm("{ .reg .u64 t; cvta.to.shared.u64 t, %1; cvt.u32.u64 %0, t; }"
        : "=r"(a) : "l"(p));
    return a;
}

__device__ __forceinline__ void cpa16(uint32_t dst, const void* src) {
    asm volatile("cp.async.cg.shared.global [%0], [%1], 16;"
                 :: "r"(dst), "l"(src) : "memory");
}

__device__ __forceinline__ void ldsm_x4(uint32_t* r, uint32_t addr) {
    asm volatile("ldmatrix.sync.aligned.m8n8.x4.shared.b16 {%0,%1,%2,%3}, [%4];"
                 : "=r"(r[0]), "=r"(r[1]), "=r"(r[2]), "=r"(r[3])
                 : "r"(addr));
}

__device__ __forceinline__ void mma16816(float* d, const uint32_t* a,
                                         uint32_t b0, uint32_t b1) {
    asm volatile(
        "mma.sync.aligned.m16n8k16.row.col.f32.bf16.bf16.f32 "
        "{%0,%1,%2,%3}, {%4,%5,%6,%7}, {%8,%9}, {%0,%1,%2,%3};"
        : "+f"(d[0]), "+f"(d[1]), "+f"(d[2]), "+f"(d[3])
        : "r"(a[0]), "r"(a[1]), "r"(a[2]), "r"(a[3]), "r"(b0), "r"(b1));
}

// ---------------------------------------------------------------------------
// 1) Convert: fp32 -> bf16 hi/lo split
// ---------------------------------------------------------------------------
__device__ __forceinline__ void split4(const float4 a, __nv_bfloat162* hi,
                                       __nv_bfloat162* lo) {
    __nv_bfloat16 h0 = __float2bfloat16_rn(a.x);
    __nv_bfloat16 h1 = __float2bfloat16_rn(a.y);
    __nv_bfloat16 h2 = __float2bfloat16_rn(a.z);
    __nv_bfloat16 h3 = __float2bfloat16_rn(a.w);
    __nv_bfloat16 l0 = __float2bfloat16_rn(a.x - __bfloat162float(h0));
    __nv_bfloat16 l1 = __float2bfloat16_rn(a.y - __bfloat162float(h1));
    __nv_bfloat16 l2 = __float2bfloat16_rn(a.z - __bfloat162float(h2));
    __nv_bfloat16 l3 = __float2bfloat16_rn(a.w - __bfloat162float(h3));
    __nv_bfloat162 v;
    v.x = h0; v.y = h1; hi[0] = v;
    v.x = h2; v.y = h3; hi[1] = v;
    v.x = l0; v.y = l1; lo[0] = v;
    v.x = l2; v.y = l3; lo[1] = v;
}

__global__ __launch_bounds__(256) void convert_kernel(const float* __restrict__ x,
                                                      const float* __restrict__ W) {
    const int gid = blockIdx.x * 256 + threadIdx.x;
    const int NX4 = (256 * 1024) / 4;
    const int NW4 = (2048 * 1024) / 4;
    if (gid < NX4) {
        float4 a = reinterpret_cast<const float4*>(x)[gid];
        split4(a,
               reinterpret_cast<__nv_bfloat162*>(g_xhi + gid * 4),
               reinterpret_cast<__nv_bfloat162*>(g_xlo + gid * 4));
    } else if (gid < NX4 + NW4) {
        int w = gid - NX4;
        float4 a = reinterpret_cast<const float4*>(W)[w];
        split4(a,
               reinterpret_cast<__nv_bfloat162*>(g_whi + w * 4),
               reinterpret_cast<__nv_bfloat162*>(g_wlo + w * 4));
    }
}

// ---------------------------------------------------------------------------
// 2) GEMM via mma.sync bf16, 3-term split as K_eff = 3*1024 = 3072.
//    CTA: 64(M) x 64(N), 4 warps of 32x32. Grid (32, 2? no: 32, 4).
//    Chunk c in [0,48): term = c>>4, koff = (c&15)*64.
//      A src: term<2 ? xhi : xlo ;  B src: term==1 ? wlo : whi
//    Fused epilogue into g_sp / g_v.
// ---------------------------------------------------------------------------
#define NSTAGE 3
#define STAGE_B 16384        // A 8K + B 8K

__global__ void __launch_bounds__(128, 1)
gemm_kernel(const float* __restrict__ q, const float* __restrict__ bias) {
    __shared__ __align__(1024) char smem[NSTAGE * STAGE_B];
    const uint32_t sb = smem_u32(smem);

    const int tid  = threadIdx.x;
    const int lane = tid & 31;
    const int wid  = tid >> 5;            // 0..3
    const int wy   = wid >> 1;            // warp m index (0/1)
    const int wx   = wid & 1;             // warp n index (0/1)
    const int gq   = lane >> 2;           // group id 0..7
    const int tq   = lane & 3;            // quad thread 0..3

    const int n0 = blockIdx.x * 64;       // 0..2047
    const int m0 = blockIdx.y * 64;       // 0..255

    // loader: 512 16B-units per tile (A and B), 4 per thread each
    auto load_stage = [&](int c, int buf) {
        const int term = c >> 4;
        const int koff = (c & 15) * 64;
        const __nv_bfloat16* As = (term < 2) ? g_xhi : g_xlo;
        const __nv_bfloat16* Bs = (term == 1) ? g_wlo : g_whi;
        const uint32_t base = sb + buf * STAGE_B;
        #pragma unroll
        for (int i = 0; i < 4; i++) {
            int u = tid + 128 * i;
            int r = u >> 3, j = u & 7;
            uint32_t swz = (uint32_t)((j ^ (r & 7)) << 4);
            cpa16(base + r * 128 + swz, As + (m0 + r) * 1024 + koff + j * 8);
            cpa16(base + 8192 + r * 128 + swz, Bs + (n0 + r) * 1024 + koff + j * 8);
        }
        asm volatile("cp.async.commit_group;" ::: "memory");
    };

    float acc[2][4][4];
    #pragma unroll
    for (int mi = 0; mi < 2; mi++)
        #pragma unroll
        for (int nj = 0; nj < 4; nj++)
            #pragma unroll
            for (int e = 0; e < 4; e++)
                acc[mi][nj][e] = 0.0f;

    load_stage(0, 0);
    load_stage(1, 1);
    load_stage(2, 2);

    const int lrow = lane & 15;           // ldmatrix row within 16
    const int lcb  = lane >> 4;           // ldmatrix 8-col block (0/1)

    for (int c = 0; c < 48; c++) {
        const int buf = c % 3;
        asm volatile("cp.async.wait_group 2;" ::: "memory");
        __syncthreads();

        const uint32_t sa = sb + buf * STAGE_B;
        const uint32_t sB = sa + 8192;

        #pragma unroll
        for (int ks = 0; ks < 4; ks++) {
            const int j = ks * 2 + lcb;
            uint32_t a[2][4], b[2][4];
            #pragma unroll
            for (int mi = 0; mi < 2; mi++) {
                int r = wy * 32 + mi * 16 + lrow;
                ldsm_x4(a[mi], sa + r * 128 + ((j ^ (r & 7)) << 4));
            }
            #pragma unroll
            for (int nb = 0; nb < 2; nb++) {
                int r = wx * 32 + nb * 16 + lrow;
                ldsm_x4(b[nb], sB + r * 128 + ((j ^ (r & 7)) << 4));
            }
            #pragma unroll
            for (int mi = 0; mi < 2; mi++)
                #pragma unroll
                for (int nj = 0; nj < 4; nj++) {
                    const int nb = nj >> 1, sub = nj & 1;
                    mma16816(acc[mi][nj], a[mi], b[nb][sub], b[nb][sub + 2]);
                }
        }
        __syncthreads();
        if (c + 3 < 48) load_stage(c + 3, buf);
        else asm volatile("cp.async.commit_group;" ::: "memory");
    }

    // ------------------------------------------------------------------
    // Fused epilogue. acc element (mi, nj, e):
    //   row = m0 + wy*32 + mi*16 + gq + (e>=2 ? 8 : 0)
    //   col = n0 + wx*32 + nj*8  + 2*tq + (e&1)
    // ------------------------------------------------------------------
    float2 bb[4];
    #pragma unroll
    for (int nj = 0; nj < 4; nj++) {
        const int col = n0 + wx * 32 + nj * 8 + 2 * tq;
        bb[nj] = *reinterpret_cast<const float2*>(bias + col);
    }

    if (n0 < 1024) {
        // k half: partial dot with q per row
        float part[4];   // slots: (mi, rh): mi*2 + rh/8
        #pragma unroll
        for (int mi = 0; mi < 2; mi++)
            #pragma unroll
            for (int rh = 0; rh < 2; rh++) {
                const int row = m0 + wy * 32 + mi * 16 + rh * 8 + gq;
                float s = 0.0f;
                #pragma unroll
                for (int nj = 0; nj < 4; nj++) {
                    const int col = n0 + wx * 32 + nj * 8 + 2 * tq;
                    float2 qq = *reinterpret_cast<const float2*>(q + row * 1024 + col);
                    s += (acc[mi][nj][rh * 2 + 0] + bb[nj].x) * qq.x;
                    s += (acc[mi][nj][rh * 2 + 1] + bb[nj].y) * qq.y;
                }
                part[mi * 2 + rh] = s;
            }
        // quad reduce over tq
        #pragma unroll
        for (int sl = 0; sl < 4; sl++) {
            part[sl] += __shfl_xor_sync(0xFFFFFFFFu, part[sl], 1);
            part[sl] += __shfl_xor_sync(0xFFFFFFFFu, part[sl], 2);
        }
        if (tq == 0) {
            const int slot = blockIdx.x * 2 + wx;    // 0..31
            #pragma unroll
            for (int sl = 0; sl < 4; sl++) {
                const int row = m0 + wy * 32 + (sl >> 1) * 16 + (sl & 1) * 8 + gq;
                g_sp[slot * 256 + row] = part[sl];
            }
        }
    } else {
        // v half: write v + bias
        #pragma unroll
        for (int mi = 0; mi < 2; mi++)
            #pragma unroll
            for (int rh = 0; rh < 2; rh++) {
                const int row = m0 + wy * 32 + mi * 16 + rh * 8 + gq;
                #pragma unroll
                for (int nj = 0; nj < 4; nj++) {
                    const int col = (n0 - 1024) + wx * 32 + nj * 8 + 2 * tq;
                    float2 o;
                    o.x = acc[mi][nj][rh * 2 + 0] + bb[nj].x;
                    o.y = acc[mi][nj][rh * 2 + 1] + bb[nj].y;
                    *reinterpret_cast<float2*>(g_v + row * 1024 + col) = o;
                }
            }
    }
}

// ---------------------------------------------------------------------------
// 3) Scale: out[b,:] = v[b,:] * sum(partials[b])
// ---------------------------------------------------------------------------
__global__ __launch_bounds__(256) void scale_kernel(float* __restrict__ out) {
    const int b = blockIdx.x;
    const int t = threadIdx.x;
    float s = 0.0f;
    #pragma unroll
    for (int j = 0; j < 32; j++) s += g_sp[j * 256 + b];
    float4 v = reinterpret_cast<const float4*>(g_v + b * 1024)[t];
    float4 o;
    o.x = v.x * s; o.y = v.y * s; o.z = v.z * s; o.w = v.w * s;
    reinterpret_cast<float4*>(out + b * 1024)[t] = o;
}

// ---------------------------------------------------------------------------
extern "C" void kernel_launch(void* const* d_in, const int* in_sizes, int n_in,
                              void* d_out, int out_size) {
    const float* x  = (const float*)d_in[0];   // 256x1024
    const float* q  = (const float*)d_in[1];   // 256x1024
    const float* W  = (const float*)d_in[2];   // 2048x1024
    const float* bs = (const float*)d_in[3];   // 2048
    float* out = (float*)d_out;                // 256x1024

    convert_kernel<<<2304, 256>>>(x, W);
    gemm_kernel<<<dim3(32, 4), 128>>>(q, bs);
    scale_kernel<<<256, 256>>>(out);
}

// round 4
// speedup vs baseline: 2.4314x; 1.1348x over previous
#include <cuda_runtime.h>
#include <cuda_bf16.h>
#include <cstdint>

// ---------------------------------------------------------------------------
// Device scratch (allocation-free)
// ---------------------------------------------------------------------------
__device__ __align__(256) __nv_bfloat16 g_xhi[256 * 1024];
__device__ __align__(256) __nv_bfloat16 g_xlo[256 * 1024];
__device__ __align__(256) __nv_bfloat16 g_whi[2048 * 1024];
__device__ __align__(256) __nv_bfloat16 g_wlo[2048 * 1024];
__device__ __align__(256) float g_vp[2 * 256 * 1024];  // partial v (+bias in z=0)
__device__ __align__(256) float g_sp[64 * 256];        // partial dots

// ---------------------------------------------------------------------------
// Helpers
// ---------------------------------------------------------------------------
__device__ __forceinline__ uint32_t smem_u32(const void* p) {
    uint32_t a;
    asm("{ .reg .u64 t; cvta.to.shared.u64 t, %1; cvt.u32.u64 %0, t; }"
        : "=r"(a) : "l"(p));
    return a;
}

__device__ __forceinline__ void cpa16(uint32_t dst, const void* src) {
    asm volatile("cp.async.cg.shared.global [%0], [%1], 16;"
                 :: "r"(dst), "l"(src) : "memory");
}

__device__ __forceinline__ void ldsm_x4(uint32_t* r, uint32_t addr) {
    asm volatile("ldmatrix.sync.aligned.m8n8.x4.shared.b16 {%0,%1,%2,%3}, [%4];"
                 : "=r"(r[0]), "=r"(r[1]), "=r"(r[2]), "=r"(r[3])
                 : "r"(addr));
}

__device__ __forceinline__ void mma16816(float* d, const uint32_t* a,
                                         uint32_t b0, uint32_t b1) {
    asm volatile(
        "mma.sync.aligned.m16n8k16.row.col.f32.bf16.bf16.f32 "
        "{%0,%1,%2,%3}, {%4,%5,%6,%7}, {%8,%9}, {%0,%1,%2,%3};"
        : "+f"(d[0]), "+f"(d[1]), "+f"(d[2]), "+f"(d[3])
        : "r"(a[0]), "r"(a[1]), "r"(a[2]), "r"(a[3]), "r"(b0), "r"(b1));
}

// ---------------------------------------------------------------------------
// 1) Convert: fp32 -> bf16 hi/lo split (2 float4 per thread for MLP)
// ---------------------------------------------------------------------------
__device__ __forceinline__ void split4(const float4 a, __nv_bfloat162* hi,
                                       __nv_bfloat162* lo) {
    __nv_bfloat16 h0 = __float2bfloat16_rn(a.x);
    __nv_bfloat16 h1 = __float2bfloat16_rn(a.y);
    __nv_bfloat16 h2 = __float2bfloat16_rn(a.z);
    __nv_bfloat16 h3 = __float2bfloat16_rn(a.w);
    __nv_bfloat16 l0 = __float2bfloat16_rn(a.x - __bfloat162float(h0));
    __nv_bfloat16 l1 = __float2bfloat16_rn(a.y - __bfloat162float(h1));
    __nv_bfloat16 l2 = __float2bfloat16_rn(a.z - __bfloat162float(h2));
    __nv_bfloat16 l3 = __float2bfloat16_rn(a.w - __bfloat162float(h3));
    __nv_bfloat162 v;
    v.x = h0; v.y = h1; hi[0] = v;
    v.x = h2; v.y = h3; hi[1] = v;
    v.x = l0; v.y = l1; lo[0] = v;
    v.x = l2; v.y = l3; lo[1] = v;
}

__global__ __launch_bounds__(256) void convert_kernel(const float* __restrict__ x,
                                                      const float* __restrict__ W) {
    const int gid = blockIdx.x * 256 + threadIdx.x;
    const int NX8 = (256 * 1024) / 8;        // 32768 pairs
    const int NW8 = (2048 * 1024) / 8;       // 262144 pairs
    if (gid < NX8) {
        float4 a0 = reinterpret_cast<const float4*>(x)[gid * 2 + 0];
        float4 a1 = reinterpret_cast<const float4*>(x)[gid * 2 + 1];
        split4(a0, reinterpret_cast<__nv_bfloat162*>(g_xhi + gid * 8),
                   reinterpret_cast<__nv_bfloat162*>(g_xlo + gid * 8));
        split4(a1, reinterpret_cast<__nv_bfloat162*>(g_xhi + gid * 8 + 4),
                   reinterpret_cast<__nv_bfloat162*>(g_xlo + gid * 8 + 4));
    } else if (gid < NX8 + NW8) {
        int w = gid - NX8;
        float4 a0 = reinterpret_cast<const float4*>(W)[w * 2 + 0];
        float4 a1 = reinterpret_cast<const float4*>(W)[w * 2 + 1];
        split4(a0, reinterpret_cast<__nv_bfloat162*>(g_whi + w * 8),
                   reinterpret_cast<__nv_bfloat162*>(g_wlo + w * 8));
        split4(a1, reinterpret_cast<__nv_bfloat162*>(g_whi + w * 8 + 4),
                   reinterpret_cast<__nv_bfloat162*>(g_wlo + w * 8 + 4));
    }
}

// ---------------------------------------------------------------------------
// 2) GEMM via mma.sync bf16, 3-term split, split-K 2.
//    CTA: 64(M) x 64(N), 4 warps of 32x32. Grid (32, 4, 2) = 256 CTAs.
//    z block handles chunks [z*24, z*24+24) of 48; term = c>>4, koff=(c&15)*64.
// ---------------------------------------------------------------------------
#define NSTAGE 3
#define STAGE_B 16384        // A 8K + B 8K

__global__ void __launch_bounds__(128, 2)
gemm_kernel(const float* __restrict__ q, const float* __restrict__ bias) {
    __shared__ __align__(1024) char smem[NSTAGE * STAGE_B];
    const uint32_t sb = smem_u32(smem);

    const int tid  = threadIdx.x;
    const int lane = tid & 31;
    const int wid  = tid >> 5;            // 0..3
    const int wy   = wid >> 1;            // warp m index (0/1)
    const int wx   = wid & 1;             // warp n index (0/1)
    const int gq   = lane >> 2;           // group id 0..7
    const int tq   = lane & 3;            // quad thread 0..3

    const int n0 = blockIdx.x * 64;       // 0..2047
    const int m0 = blockIdx.y * 64;       // 0..255
    const int z  = blockIdx.z;            // split-K half
    const int c0 = z * 24;

    auto load_stage = [&](int c, int buf) {
        const int term = c >> 4;
        const int koff = (c & 15) * 64;
        const __nv_bfloat16* As = (term < 2) ? g_xhi : g_xlo;
        const __nv_bfloat16* Bs = (term == 1) ? g_wlo : g_whi;
        const uint32_t base = sb + buf * STAGE_B;
        #pragma unroll
        for (int i = 0; i < 4; i++) {
            int u = tid + 128 * i;
            int r = u >> 3, j = u & 7;
            uint32_t swz = (uint32_t)((j ^ (r & 7)) << 4);
            cpa16(base + r * 128 + swz, As + (m0 + r) * 1024 + koff + j * 8);
            cpa16(base + 8192 + r * 128 + swz, Bs + (n0 + r) * 1024 + koff + j * 8);
        }
        asm volatile("cp.async.commit_group;" ::: "memory");
    };

    float acc[2][4][4];
    #pragma unroll
    for (int mi = 0; mi < 2; mi++)
        #pragma unroll
        for (int nj = 0; nj < 4; nj++)
            #pragma unroll
            for (int e = 0; e < 4; e++)
                acc[mi][nj][e] = 0.0f;

    load_stage(c0 + 0, 0);
    load_stage(c0 + 1, 1);
    load_stage(c0 + 2, 2);

    const int lrow = lane & 15;
    const int lcb  = lane >> 4;

    for (int i = 0; i < 24; i++) {
        const int buf = i % 3;
        asm volatile("cp.async.wait_group 2;" ::: "memory");
        __syncthreads();

        const uint32_t sa = sb + buf * STAGE_B;
        const uint32_t sB = sa + 8192;

        #pragma unroll
        for (int ks = 0; ks < 4; ks++) {
            const int j = ks * 2 + lcb;
            uint32_t a[2][4], b[2][4];
            #pragma unroll
            for (int mi = 0; mi < 2; mi++) {
                int r = wy * 32 + mi * 16 + lrow;
                ldsm_x4(a[mi], sa + r * 128 + ((j ^ (r & 7)) << 4));
            }
            #pragma unroll
            for (int nb = 0; nb < 2; nb++) {
                int r = wx * 32 + nb * 16 + lrow;
                ldsm_x4(b[nb], sB + r * 128 + ((j ^ (r & 7)) << 4));
            }
            #pragma unroll
            for (int mi = 0; mi < 2; mi++)
                #pragma unroll
                for (int nj = 0; nj < 4; nj++) {
                    const int nb = nj >> 1, sub = nj & 1;
                    mma16816(acc[mi][nj], a[mi], b[nb][sub], b[nb][sub + 2]);
                }
        }
        __syncthreads();
        if (i + 3 < 24) load_stage(c0 + i + 3, buf);
        else asm volatile("cp.async.commit_group;" ::: "memory");
    }

    // ------------------------------------------------------------------
    // Fused epilogue. acc element (mi, nj, e):
    //   row = m0 + wy*32 + mi*16 + gq + (e>=2 ? 8 : 0)
    //   col = n0 + wx*32 + nj*8  + 2*tq + (e&1)
    // Bias added only by the z==0 half.
    // ------------------------------------------------------------------
    float2 bb[4];
    #pragma unroll
    for (int nj = 0; nj < 4; nj++) {
        if (z == 0) {
            const int col = n0 + wx * 32 + nj * 8 + 2 * tq;
            bb[nj] = *reinterpret_cast<const float2*>(bias + col);
        } else {
            bb[nj].x = 0.0f; bb[nj].y = 0.0f;
        }
    }

    if (n0 < 1024) {
        // k half: partial dot with q per row
        float part[4];
        #pragma unroll
        for (int mi = 0; mi < 2; mi++)
            #pragma unroll
            for (int rh = 0; rh < 2; rh++) {
                const int row = m0 + wy * 32 + mi * 16 + rh * 8 + gq;
                float s = 0.0f;
                #pragma unroll
                for (int nj = 0; nj < 4; nj++) {
                    const int col = n0 + wx * 32 + nj * 8 + 2 * tq;
                    float2 qq = *reinterpret_cast<const float2*>(q + row * 1024 + col);
                    s += (acc[mi][nj][rh * 2 + 0] + bb[nj].x) * qq.x;
                    s += (acc[mi][nj][rh * 2 + 1] + bb[nj].y) * qq.y;
                }
                part[mi * 2 + rh] = s;
            }
        #pragma unroll
        for (int sl = 0; sl < 4; sl++) {
            part[sl] += __shfl_xor_sync(0xFFFFFFFFu, part[sl], 1);
            part[sl] += __shfl_xor_sync(0xFFFFFFFFu, part[sl], 2);
        }
        if (tq == 0) {
            const int slot = z * 32 + blockIdx.x * 2 + wx;   // 0..63
            #pragma unroll
            for (int sl = 0; sl < 4; sl++) {
                const int row = m0 + wy * 32 + (sl >> 1) * 16 + (sl & 1) * 8 + gq;
                g_sp[slot * 256 + row] = part[sl];
            }
        }
    } else {
        // v half: write partial v (+bias for z=0)
        float* vbase = g_vp + z * 256 * 1024;
        #pragma unroll
        for (int mi = 0; mi < 2; mi++)
            #pragma unroll
            for (int rh = 0; rh < 2; rh++) {
                const int row = m0 + wy * 32 + mi * 16 + rh * 8 + gq;
                #pragma unroll
                for (int nj = 0; nj < 4; nj++) {
                    const int col = (n0 - 1024) + wx * 32 + nj * 8 + 2 * tq;
                    float2 o;
                    o.x = acc[mi][nj][rh * 2 + 0] + bb[nj].x;
                    o.y = acc[mi][nj][rh * 2 + 1] + bb[nj].y;
                    *reinterpret_cast<float2*>(vbase + row * 1024 + col) = o;
                }
            }
    }
}

// ---------------------------------------------------------------------------
// 3) Scale: out[b,:] = (v0[b,:]+v1[b,:]) * sum(partials[b])
// ---------------------------------------------------------------------------
__global__ __launch_bounds__(256) void scale_kernel(float* __restrict__ out) {
    const int b = blockIdx.x;
    const int t = threadIdx.x;
    float s = 0.0f;
    #pragma unroll
    for (int j = 0; j < 64; j++) s += g_sp[j * 256 + b];
    float4 v0 = reinterpret_cast<const float4*>(g_vp + b * 1024)[t];
    float4 v1 = reinterpret_cast<const float4*>(g_vp + 256 * 1024 + b * 1024)[t];
    float4 o;
    o.x = (v0.x + v1.x) * s;
    o.y = (v0.y + v1.y) * s;
    o.z = (v0.z + v1.z) * s;
    o.w = (v0.w + v1.w) * s;
    reinterpret_cast<float4*>(out + b * 1024)[t] = o;
}

// ---------------------------------------------------------------------------
extern "C" void kernel_launch(void* const* d_in, const int* in_sizes, int n_in,
                              void* d_out, int out_size) {
    const float* x  = (const float*)d_in[0];   // 256x1024
    const float* q  = (const float*)d_in[1];   // 256x1024
    const float* W  = (const float*)d_in[2];   // 2048x1024
    const float* bs = (const float*)d_in[3];   // 2048
    float* out = (float*)d_out;                // 256x1024

    convert_kernel<<<1152, 256>>>(x, W);
    gemm_kernel<<<dim3(32, 4, 2), 128>>>(q, bs);
    scale_kernel<<<256, 256>>>(out);
}

// round 5
// speedup vs baseline: 3.0952x; 1.2730x over previous
#include <cuda_runtime.h>
#include <cuda_fp16.h>
#include <cstdint>

// ---------------------------------------------------------------------------
// Device scratch (allocation-free)
// ---------------------------------------------------------------------------
__device__ __align__(256) __half g_xhi[256 * 1024];
__device__ __align__(256) __half g_xlo[256 * 1024];
__device__ __align__(256) __half g_wh[2048 * 1024];
__device__ __align__(256) float g_vp[2 * 256 * 1024];  // partial v (+bias in z=0)
__device__ __align__(256) float g_sp[64 * 256];        // partial dots

// ---------------------------------------------------------------------------
// Helpers
// ---------------------------------------------------------------------------
__device__ __forceinline__ uint32_t smem_u32(const void* p) {
    uint32_t a;
    asm("{ .reg .u64 t; cvta.to.shared.u64 t, %1; cvt.u32.u64 %0, t; }"
        : "=r"(a) : "l"(p));
    return a;
}

__device__ __forceinline__ void cpa16(uint32_t dst, const void* src) {
    asm volatile("cp.async.cg.shared.global [%0], [%1], 16;"
                 :: "r"(dst), "l"(src) : "memory");
}

__device__ __forceinline__ void ldsm_x4(uint32_t* r, uint32_t addr) {
    asm volatile("ldmatrix.sync.aligned.m8n8.x4.shared.b16 {%0,%1,%2,%3}, [%4];"
                 : "=r"(r[0]), "=r"(r[1]), "=r"(r[2]), "=r"(r[3])
                 : "r"(addr));
}

__device__ __forceinline__ void mma16816(float* d, const uint32_t* a,
                                         uint32_t b0, uint32_t b1) {
    asm volatile(
        "mma.sync.aligned.m16n8k16.row.col.f32.f16.f16.f32 "
        "{%0,%1,%2,%3}, {%4,%5,%6,%7}, {%8,%9}, {%0,%1,%2,%3};"
        : "+f"(d[0]), "+f"(d[1]), "+f"(d[2]), "+f"(d[3])
        : "r"(a[0]), "r"(a[1]), "r"(a[2]), "r"(a[3]), "r"(b0), "r"(b1));
}

// ---------------------------------------------------------------------------
// 1) Convert: x -> fp16 hi/lo split (exact to 21 bits); W -> fp16 (rn).
//    Each thread handles 8 floats; all stores are packed 16B.
// ---------------------------------------------------------------------------
__device__ __forceinline__ uint4 pack_hi8(const float4 a0, const float4 a1) {
    __half2 h0 = __floats2half2_rn(a0.x, a0.y);
    __half2 h1 = __floats2half2_rn(a0.z, a0.w);
    __half2 h2 = __floats2half2_rn(a1.x, a1.y);
    __half2 h3 = __floats2half2_rn(a1.z, a1.w);
    uint4 u;
    u.x = *reinterpret_cast<uint32_t*>(&h0);
    u.y = *reinterpret_cast<uint32_t*>(&h1);
    u.z = *reinterpret_cast<uint32_t*>(&h2);
    u.w = *reinterpret_cast<uint32_t*>(&h3);
    return u;
}

__device__ __forceinline__ uint4 pack_lo8(const float4 a0, const float4 a1,
                                          const uint4 hi) {
    float2 f0 = __half22float2(*reinterpret_cast<const __half2*>(&hi.x));
    float2 f1 = __half22float2(*reinterpret_cast<const __half2*>(&hi.y));
    float2 f2 = __half22float2(*reinterpret_cast<const __half2*>(&hi.z));
    float2 f3 = __half22float2(*reinterpret_cast<const __half2*>(&hi.w));
    __half2 l0 = __floats2half2_rn(a0.x - f0.x, a0.y - f0.y);
    __half2 l1 = __floats2half2_rn(a0.z - f1.x, a0.w - f1.y);
    __half2 l2 = __floats2half2_rn(a1.x - f2.x, a1.y - f2.y);
    __half2 l3 = __floats2half2_rn(a1.z - f3.x, a1.w - f3.y);
    uint4 u;
    u.x = *reinterpret_cast<uint32_t*>(&l0);
    u.y = *reinterpret_cast<uint32_t*>(&l1);
    u.z = *reinterpret_cast<uint32_t*>(&l2);
    u.w = *reinterpret_cast<uint32_t*>(&l3);
    return u;
}

__global__ __launch_bounds__(256) void convert_kernel(const float* __restrict__ x,
                                                      const float* __restrict__ W) {
    const int gid = blockIdx.x * 256 + threadIdx.x;
    const int NX8 = (256 * 1024) / 8;        // 32768
    const int NW8 = (2048 * 1024) / 8;       // 262144
    if (gid < NX8) {
        float4 a0 = reinterpret_cast<const float4*>(x)[gid * 2 + 0];
        float4 a1 = reinterpret_cast<const float4*>(x)[gid * 2 + 1];
        uint4 hi = pack_hi8(a0, a1);
        uint4 lo = pack_lo8(a0, a1, hi);
        reinterpret_cast<uint4*>(g_xhi)[gid] = hi;
        reinterpret_cast<uint4*>(g_xlo)[gid] = lo;
    } else if (gid < NX8 + NW8) {
        int w = gid - NX8;
        float4 a0 = reinterpret_cast<const float4*>(W)[w * 2 + 0];
        float4 a1 = reinterpret_cast<const float4*>(W)[w * 2 + 1];
        reinterpret_cast<uint4*>(g_wh)[w] = pack_hi8(a0, a1);
    }
}

// ---------------------------------------------------------------------------
// 2) GEMM via mma.sync fp16, 2-term x split, split-K 2.
//    CTA: 64(M) x 64(N), 4 warps of 32x32. Grid (32, 4, 2) = 256 CTAs.
//    32 chunks total: term = c>>4 (x_hi / x_lo), koff = (c&15)*64, B = W_h.
// ---------------------------------------------------------------------------
#define NSTAGE 3
#define STAGE_B 16384        // A 8K + B 8K

__global__ void __launch_bounds__(128, 2)
gemm_kernel(const float* __restrict__ q, const float* __restrict__ bias) {
    __shared__ __align__(1024) char smem[NSTAGE * STAGE_B];
    const uint32_t sb = smem_u32(smem);

    const int tid  = threadIdx.x;
    const int lane = tid & 31;
    const int wid  = tid >> 5;            // 0..3
    const int wy   = wid >> 1;            // warp m index (0/1)
    const int wx   = wid & 1;             // warp n index (0/1)
    const int gq   = lane >> 2;           // group id 0..7
    const int tq   = lane & 3;            // quad thread 0..3

    const int n0 = blockIdx.x * 64;       // 0..2047
    const int m0 = blockIdx.y * 64;       // 0..255
    const int z  = blockIdx.z;            // split-K half
    const int c0 = z * 16;

    auto load_stage = [&](int c, int buf) {
        const int term = c >> 4;          // 0: x_hi, 1: x_lo
        const int koff = (c & 15) * 64;
        const __half* As = term ? g_xlo : g_xhi;
        const uint32_t base = sb + buf * STAGE_B;
        #pragma unroll
        for (int i = 0; i < 4; i++) {
            int u = tid + 128 * i;
            int r = u >> 3, j = u & 7;
            uint32_t swz = (uint32_t)((j ^ (r & 7)) << 4);
            cpa16(base + r * 128 + swz, As + (m0 + r) * 1024 + koff + j * 8);
            cpa16(base + 8192 + r * 128 + swz, g_wh + (n0 + r) * 1024 + koff + j * 8);
        }
        asm volatile("cp.async.commit_group;" ::: "memory");
    };

    float acc[2][4][4];
    #pragma unroll
    for (int mi = 0; mi < 2; mi++)
        #pragma unroll
        for (int nj = 0; nj < 4; nj++)
            #pragma unroll
            for (int e = 0; e < 4; e++)
                acc[mi][nj][e] = 0.0f;

    load_stage(c0 + 0, 0);
    load_stage(c0 + 1, 1);
    load_stage(c0 + 2, 2);

    const int lrow = lane & 15;
    const int lcb  = lane >> 4;

    for (int i = 0; i < 16; i++) {
        const int buf = i % 3;
        asm volatile("cp.async.wait_group 2;" ::: "memory");
        __syncthreads();

        const uint32_t sa = sb + buf * STAGE_B;
        const uint32_t sB = sa + 8192;

        #pragma unroll
        for (int ks = 0; ks < 4; ks++) {
            const int j = ks * 2 + lcb;
            uint32_t a[2][4], b[2][4];
            #pragma unroll
            for (int mi = 0; mi < 2; mi++) {
                int r = wy * 32 + mi * 16 + lrow;
                ldsm_x4(a[mi], sa + r * 128 + ((j ^ (r & 7)) << 4));
            }
            #pragma unroll
            for (int nb = 0; nb < 2; nb++) {
                int r = wx * 32 + nb * 16 + lrow;
                ldsm_x4(b[nb], sB + r * 128 + ((j ^ (r & 7)) << 4));
            }
            #pragma unroll
            for (int mi = 0; mi < 2; mi++)
                #pragma unroll
                for (int nj = 0; nj < 4; nj++) {
                    const int nb = nj >> 1, sub = nj & 1;
                    mma16816(acc[mi][nj], a[mi], b[nb][sub], b[nb][sub + 2]);
                }
        }
        __syncthreads();
        if (i + 3 < 16) load_stage(c0 + i + 3, buf);
        else asm volatile("cp.async.commit_group;" ::: "memory");
    }

    // ------------------------------------------------------------------
    // Fused epilogue. acc element (mi, nj, e):
    //   row = m0 + wy*32 + mi*16 + gq + (e>=2 ? 8 : 0)
    //   col = n0 + wx*32 + nj*8  + 2*tq + (e&1)
    // Bias added only by the z==0 half.
    // ------------------------------------------------------------------
    float2 bb[4];
    #pragma unroll
    for (int nj = 0; nj < 4; nj++) {
        if (z == 0) {
            const int col = n0 + wx * 32 + nj * 8 + 2 * tq;
            bb[nj] = *reinterpret_cast<const float2*>(bias + col);
        } else {
            bb[nj].x = 0.0f; bb[nj].y = 0.0f;
        }
    }

    if (n0 < 1024) {
        // k half: partial dot with q per row
        float part[4];
        #pragma unroll
        for (int mi = 0; mi < 2; mi++)
            #pragma unroll
            for (int rh = 0; rh < 2; rh++) {
                const int row = m0 + wy * 32 + mi * 16 + rh * 8 + gq;
                float s = 0.0f;
                #pragma unroll
                for (int nj = 0; nj < 4; nj++) {
                    const int col = n0 + wx * 32 + nj * 8 + 2 * tq;
                    float2 qq = *reinterpret_cast<const float2*>(q + row * 1024 + col);
                    s += (acc[mi][nj][rh * 2 + 0] + bb[nj].x) * qq.x;
                    s += (acc[mi][nj][rh * 2 + 1] + bb[nj].y) * qq.y;
                }
                part[mi * 2 + rh] = s;
            }
        #pragma unroll
        for (int sl = 0; sl < 4; sl++) {
            part[sl] += __shfl_xor_sync(0xFFFFFFFFu, part[sl], 1);
            part[sl] += __shfl_xor_sync(0xFFFFFFFFu, part[sl], 2);
        }
        if (tq == 0) {
            const int slot = z * 32 + blockIdx.x * 2 + wx;   // 0..63
            #pragma unroll
            for (int sl = 0; sl < 4; sl++) {
                const int row = m0 + wy * 32 + (sl >> 1) * 16 + (sl & 1) * 8 + gq;
                g_sp[slot * 256 + row] = part[sl];
            }
        }
    } else {
        // v half: write partial v (+bias for z=0)
        float* vbase = g_vp + z * 256 * 1024;
        #pragma unroll
        for (int mi = 0; mi < 2; mi++)
            #pragma unroll
            for (int rh = 0; rh < 2; rh++) {
                const int row = m0 + wy * 32 + mi * 16 + rh * 8 + gq;
                #pragma unroll
                for (int nj = 0; nj < 4; nj++) {
                    const int col = (n0 - 1024) + wx * 32 + nj * 8 + 2 * tq;
                    float2 o;
                    o.x = acc[mi][nj][rh * 2 + 0] + bb[nj].x;
                    o.y = acc[mi][nj][rh * 2 + 1] + bb[nj].y;
                    *reinterpret_cast<float2*>(vbase + row * 1024 + col) = o;
                }
            }
    }
}

// ---------------------------------------------------------------------------
// 3) Scale: out[b,:] = (v0[b,:]+v1[b,:]) * sum(partials[b])
// ---------------------------------------------------------------------------
__global__ __launch_bounds__(256) void scale_kernel(float* __restrict__ out) {
    const int b = blockIdx.x;
    const int t = threadIdx.x;
    float s = 0.0f;
    #pragma unroll
    for (int j = 0; j < 64; j++) s += g_sp[j * 256 + b];
    float4 v0 = reinterpret_cast<const float4*>(g_vp + b * 1024)[t];
    float4 v1 = reinterpret_cast<const float4*>(g_vp + 256 * 1024 + b * 1024)[t];
    float4 o;
    o.x = (v0.x + v1.x) * s;
    o.y = (v0.y + v1.y) * s;
    o.z = (v0.z + v1.z) * s;
    o.w = (v0.w + v1.w) * s;
    reinterpret_cast<float4*>(out + b * 1024)[t] = o;
}

// ---------------------------------------------------------------------------
extern "C" void kernel_launch(void* const* d_in, const int* in_sizes, int n_in,
                              void* d_out, int out_size) {
    const float* x  = (const float*)d_in[0];   // 256x1024
    const float* q  = (const float*)d_in[1];   // 256x1024
    const float* W  = (const float*)d_in[2];   // 2048x1024
    const float* bs = (const float*)d_in[3];   // 2048
    float* out = (float*)d_out;                // 256x1024

    convert_kernel<<<1152, 256>>>(x, W);
    gemm_kernel<<<dim3(32, 4, 2), 128>>>(q, bs);
    scale_kernel<<<256, 256>>>(out);
}

// round 6
// speedup vs baseline: 3.8674x; 1.2495x over previous
#include <cuda_runtime.h>
#include <cuda_fp16.h>
#include <cstdint>

// ---------------------------------------------------------------------------
// Device scratch (allocation-free)
// ---------------------------------------------------------------------------
__device__ __align__(256) __half g_xh[256 * 1024];
__device__ __align__(256) __half g_wh[2048 * 1024];
__device__ __align__(256) float g_vp[2 * 256 * 1024];  // partial v (+bias in z=0)
__device__ __align__(256) float g_sp[64 * 256];        // partial dots

// ---------------------------------------------------------------------------
// Helpers
// ---------------------------------------------------------------------------
__device__ __forceinline__ uint32_t smem_u32(const void* p) {
    uint32_t a;
    asm("{ .reg .u64 t; cvta.to.shared.u64 t, %1; cvt.u32.u64 %0, t; }"
        : "=r"(a) : "l"(p));
    return a;
}

__device__ __forceinline__ void cpa16(uint32_t dst, const void* src) {
    asm volatile("cp.async.cg.shared.global [%0], [%1], 16;"
                 :: "r"(dst), "l"(src) : "memory");
}

__device__ __forceinline__ void ldsm_x4(uint32_t* r, uint32_t addr) {
    asm volatile("ldmatrix.sync.aligned.m8n8.x4.shared.b16 {%0,%1,%2,%3}, [%4];"
                 : "=r"(r[0]), "=r"(r[1]), "=r"(r[2]), "=r"(r[3])
                 : "r"(addr));
}

__device__ __forceinline__ void mma16816(float* d, const uint32_t* a,
                                         uint32_t b0, uint32_t b1) {
    asm volatile(
        "mma.sync.aligned.m16n8k16.row.col.f32.f16.f16.f32 "
        "{%0,%1,%2,%3}, {%4,%5,%6,%7}, {%8,%9}, {%0,%1,%2,%3};"
        : "+f"(d[0]), "+f"(d[1]), "+f"(d[2]), "+f"(d[3])
        : "r"(a[0]), "r"(a[1]), "r"(a[2]), "r"(a[3]), "r"(b0), "r"(b1));
}

// ---------------------------------------------------------------------------
// 1) Convert: fp32 -> fp16 (rn). Each thread: 16 floats, 4 independent
//    float4 loads (MLP=4), 2x uint4 packed stores.
//    x: 16384 threads, W: 131072 threads -> 576 blocks of 256.
// ---------------------------------------------------------------------------
__device__ __forceinline__ uint4 pack_hi8(const float4 a0, const float4 a1) {
    __half2 h0 = __floats2half2_rn(a0.x, a0.y);
    __half2 h1 = __floats2half2_rn(a0.z, a0.w);
    __half2 h2 = __floats2half2_rn(a1.x, a1.y);
    __half2 h3 = __floats2half2_rn(a1.z, a1.w);
    uint4 u;
    u.x = *reinterpret_cast<uint32_t*>(&h0);
    u.y = *reinterpret_cast<uint32_t*>(&h1);
    u.z = *reinterpret_cast<uint32_t*>(&h2);
    u.w = *reinterpret_cast<uint32_t*>(&h3);
    return u;
}

__global__ __launch_bounds__(256) void convert_kernel(const float* __restrict__ x,
                                                      const float* __restrict__ W) {
    const int gid = blockIdx.x * 256 + threadIdx.x;
    const int NX16 = (256 * 1024) / 16;      // 16384
    const int NW16 = (2048 * 1024) / 16;     // 131072

    const float* src;
    __half* dst;
    int idx;
    if (gid < NX16) {
        src = x; dst = g_xh; idx = gid;
    } else if (gid < NX16 + NW16) {
        src = W; dst = g_wh; idx = gid - NX16;
    } else {
        return;
    }

    const float4* s4 = reinterpret_cast<const float4*>(src) + idx * 4;
    float4 a0 = s4[0];
    float4 a1 = s4[1];
    float4 a2 = s4[2];
    float4 a3 = s4[3];
    uint4* d4 = reinterpret_cast<uint4*>(dst + idx * 16);
    d4[0] = pack_hi8(a0, a1);
    d4[1] = pack_hi8(a2, a3);
}

// ---------------------------------------------------------------------------
// 2) GEMM via mma.sync fp16, single term, split-K 2.
//    CTA: 64(M) x 64(N), 4 warps of 32x32. Grid (32, 4, 2) = 256 CTAs.
//    z handles k-chunks [z*8, z*8+8) of 16 (chunk = 64 k).
// ---------------------------------------------------------------------------
#define NSTAGE 3
#define STAGE_B 16384        // A 8K + B 8K

__global__ void __launch_bounds__(128, 2)
gemm_kernel(const float* __restrict__ q, const float* __restrict__ bias) {
    __shared__ __align__(1024) char smem[NSTAGE * STAGE_B];
    const uint32_t sb = smem_u32(smem);

    const int tid  = threadIdx.x;
    const int lane = tid & 31;
    const int wid  = tid >> 5;            // 0..3
    const int wy   = wid >> 1;            // warp m index (0/1)
    const int wx   = wid & 1;             // warp n index (0/1)
    const int gq   = lane >> 2;           // group id 0..7
    const int tq   = lane & 3;            // quad thread 0..3

    const int n0 = blockIdx.x * 64;       // 0..2047
    const int m0 = blockIdx.y * 64;       // 0..255
    const int z  = blockIdx.z;            // split-K half
    const int c0 = z * 8;

    auto load_stage = [&](int c, int buf) {
        const int koff = c * 64;
        const uint32_t base = sb + buf * STAGE_B;
        #pragma unroll
        for (int i = 0; i < 4; i++) {
            int u = tid + 128 * i;
            int r = u >> 3, j = u & 7;
            uint32_t swz = (uint32_t)((j ^ (r & 7)) << 4);
            cpa16(base + r * 128 + swz, g_xh + (m0 + r) * 1024 + koff + j * 8);
            cpa16(base + 8192 + r * 128 + swz, g_wh + (n0 + r) * 1024 + koff + j * 8);
        }
        asm volatile("cp.async.commit_group;" ::: "memory");
    };

    float acc[2][4][4];
    #pragma unroll
    for (int mi = 0; mi < 2; mi++)
        #pragma unroll
        for (int nj = 0; nj < 4; nj++)
            #pragma unroll
            for (int e = 0; e < 4; e++)
                acc[mi][nj][e] = 0.0f;

    load_stage(c0 + 0, 0);
    load_stage(c0 + 1, 1);
    load_stage(c0 + 2, 2);

    const int lrow = lane & 15;
    const int lcb  = lane >> 4;

    for (int i = 0; i < 8; i++) {
        const int buf = i % 3;
        asm volatile("cp.async.wait_group 2;" ::: "memory");
        __syncthreads();

        const uint32_t sa = sb + buf * STAGE_B;
        const uint32_t sB = sa + 8192;

        #pragma unroll
        for (int ks = 0; ks < 4; ks++) {
            const int j = ks * 2 + lcb;
            uint32_t a[2][4], b[2][4];
            #pragma unroll
            for (int mi = 0; mi < 2; mi++) {
                int r = wy * 32 + mi * 16 + lrow;
                ldsm_x4(a[mi], sa + r * 128 + ((j ^ (r & 7)) << 4));
            }
            #pragma unroll
            for (int nb = 0; nb < 2; nb++) {
                int r = wx * 32 + nb * 16 + lrow;
                ldsm_x4(b[nb], sB + r * 128 + ((j ^ (r & 7)) << 4));
            }
            #pragma unroll
            for (int mi = 0; mi < 2; mi++)
                #pragma unroll
                for (int nj = 0; nj < 4; nj++) {
                    const int nb = nj >> 1, sub = nj & 1;
                    mma16816(acc[mi][nj], a[mi], b[nb][sub], b[nb][sub + 2]);
                }
        }
        __syncthreads();
        if (i + 3 < 8) load_stage(c0 + i + 3, buf);
        else asm volatile("cp.async.commit_group;" ::: "memory");
    }

    // ------------------------------------------------------------------
    // Fused epilogue. acc element (mi, nj, e):
    //   row = m0 + wy*32 + mi*16 + gq + (e>=2 ? 8 : 0)
    //   col = n0 + wx*32 + nj*8  + 2*tq + (e&1)
    // Bias added only by the z==0 half.
    // ------------------------------------------------------------------
    float2 bb[4];
    #pragma unroll
    for (int nj = 0; nj < 4; nj++) {
        if (z == 0) {
            const int col = n0 + wx * 32 + nj * 8 + 2 * tq;
            bb[nj] = *reinterpret_cast<const float2*>(bias + col);
        } else {
            bb[nj].x = 0.0f; bb[nj].y = 0.0f;
        }
    }

    if (n0 < 1024) {
        // k half: partial dot with q per row
        float part[4];
        #pragma unroll
        for (int mi = 0; mi < 2; mi++)
            #pragma unroll
            for (int rh = 0; rh < 2; rh++) {
                const int row = m0 + wy * 32 + mi * 16 + rh * 8 + gq;
                float s = 0.0f;
                #pragma unroll
                for (int nj = 0; nj < 4; nj++) {
                    const int col = n0 + wx * 32 + nj * 8 + 2 * tq;
                    float2 qq = *reinterpret_cast<const float2*>(q + row * 1024 + col);
                    s += (acc[mi][nj][rh * 2 + 0] + bb[nj].x) * qq.x;
                    s += (acc[mi][nj][rh * 2 + 1] + bb[nj].y) * qq.y;
                }
                part[mi * 2 + rh] = s;
            }
        #pragma unroll
        for (int sl = 0; sl < 4; sl++) {
            part[sl] += __shfl_xor_sync(0xFFFFFFFFu, part[sl], 1);
            part[sl] += __shfl_xor_sync(0xFFFFFFFFu, part[sl], 2);
        }
        if (tq == 0) {
            const int slot = z * 32 + blockIdx.x * 2 + wx;   // 0..63
            #pragma unroll
            for (int sl = 0; sl < 4; sl++) {
                const int row = m0 + wy * 32 + (sl >> 1) * 16 + (sl & 1) * 8 + gq;
                g_sp[slot * 256 + row] = part[sl];
            }
        }
    } else {
        // v half: write partial v (+bias for z=0)
        float* vbase = g_vp + z * 256 * 1024;
        #pragma unroll
        for (int mi = 0; mi < 2; mi++)
            #pragma unroll
            for (int rh = 0; rh < 2; rh++) {
                const int row = m0 + wy * 32 + mi * 16 + rh * 8 + gq;
                #pragma unroll
                for (int nj = 0; nj < 4; nj++) {
                    const int col = (n0 - 1024) + wx * 32 + nj * 8 + 2 * tq;
                    float2 o;
                    o.x = acc[mi][nj][rh * 2 + 0] + bb[nj].x;
                    o.y = acc[mi][nj][rh * 2 + 1] + bb[nj].y;
                    *reinterpret_cast<float2*>(vbase + row * 1024 + col) = o;
                }
            }
    }
}

// ---------------------------------------------------------------------------
// 3) Scale: out[b,:] = (v0[b,:]+v1[b,:]) * sum(partials[b])
// ---------------------------------------------------------------------------
__global__ __launch_bounds__(256) void scale_kernel(float* __restrict__ out) {
    const int b = blockIdx.x;
    const int t = threadIdx.x;
    float s = 0.0f;
    #pragma unroll
    for (int j = 0; j < 64; j++) s += g_sp[j * 256 + b];
    float4 v0 = reinterpret_cast<const float4*>(g_vp + b * 1024)[t];
    float4 v1 = reinterpret_cast<const float4*>(g_vp + 256 * 1024 + b * 1024)[t];
    float4 o;
    o.x = (v0.x + v1.x) * s;
    o.y = (v0.y + v1.y) * s;
    o.z = (v0.z + v1.z) * s;
    o.w = (v0.w + v1.w) * s;
    reinterpret_cast<float4*>(out + b * 1024)[t] = o;
}

// ---------------------------------------------------------------------------
extern "C" void kernel_launch(void* const* d_in, const int* in_sizes, int n_in,
                              void* d_out, int out_size) {
    const float* x  = (const float*)d_in[0];   // 256x1024
    const float* q  = (const float*)d_in[1];   // 256x1024
    const float* W  = (const float*)d_in[2];   // 2048x1024
    const float* bs = (const float*)d_in[3];   // 2048
    float* out = (float*)d_out;                // 256x1024

    convert_kernel<<<576, 256>>>(x, W);
    gemm_kernel<<<dim3(32, 4, 2), 128>>>(q, bs);
    scale_kernel<<<256, 256>>>(out);
}